// round 3
// baseline (speedup 1.0000x reference)
#include <cuda_runtime.h>
#include <cuda_bf16.h>
#include <cstdint>

#define GR 8
#define BATCH 32
#define TT 512
#define HGD 128
#define ROWS 384          // 3 * HGD
#define PADW 388          // smem row stride (floats) for W[k][o] (phase 1)
#define PADX 34           // smem row stride for x[k][b] (phase 1)
#define HPAD 144          // gru h buffer: 4 chunks of 32, stride 36

typedef unsigned long long ull;

// 201 MB scratch for gx[t][g][o][b]
__device__ float g_gx[(size_t)TT * GR * ROWS * BATCH];

__device__ __forceinline__ ull pk(float lo, float hi) {
    ull r;
    asm("mov.b64 %0, {%1, %2};" : "=l"(r) : "f"(lo), "f"(hi));
    return r;
}
__device__ __forceinline__ float2 up(ull v) {
    float2 r;
    asm("mov.b64 {%0, %1}, %2;" : "=f"(r.x), "=f"(r.y) : "l"(v));
    return r;
}
__device__ __forceinline__ void fma2(ull& d, ull a, ull b) {
    asm("fma.rn.f32x2 %0, %1, %2, %0;" : "+l"(d) : "l"(a), "l"(b));
}

__device__ __forceinline__ float sigm(float x) {
    return __fdividef(1.0f, 1.0f + __expf(-x));
}
__device__ __forceinline__ float tanh_(float x) {
    return 1.0f - __fdividef(2.0f, __expf(2.0f * x) + 1.0f);
}
__device__ __forceinline__ float hadd(ull v) {
    float2 u = up(v);
    return u.x + u.y;
}

// ============================================================================
// Phase 1: gx[t][g][o][b] = b_ih[g][o] + sum_i W_ih[g][o][i] * x[b][t][g*128+i]
// Grid: 128 CTAs = (tb 0..15) x (g 0..7), 256 threads, W_ih[g] resident in smem.
// Weight f32x2 pairs read directly as ulonglong2 (o-contiguous) — no packing
// instructions in the inner loop.
// ============================================================================
__global__ void __launch_bounds__(256, 1)
gx_kernel(const float* __restrict__ x,
          const float* __restrict__ W_ih,
          const float* __restrict__ b_ih)
{
    extern __shared__ float sm[];
    float* Ws = sm;                   // [128][PADW]   W[k][o]
    float* Xs = sm + 128 * PADW;      // [128][PADX]   x[k][b]

    const int g  = blockIdx.x & 7;
    const int tb = blockIdx.x >> 3;
    const int tid = threadIdx.x;

    // Load W_ih[g] transposed to k-major
    const float* Wg = W_ih + (size_t)g * ROWS * 128;
    for (int idx = tid; idx < ROWS * 128; idx += 256) {
        int o = idx >> 7, k = idx & 127;
        Ws[k * PADW + o] = Wg[idx];
    }

    const int w    = tid >> 5;
    const int lane = tid & 31;
    const int rsub = lane >> 3;       // 0..3
    const int bq   = lane & 7;        // 0..7
    const int ro   = w * 48 + rsub * 12;   // 12 rows per thread
    const int bb   = bq * 4;               // 4 batches per thread

    float bias[12];
#pragma unroll
    for (int i = 0; i < 12; i++) bias[i] = b_ih[g * ROWS + ro + i];

    __syncthreads();

    for (int tt = 0; tt < 32; tt++) {
        const int t = tb * 32 + tt;

        // Load x tile [32 b][128 k] -> Xs[k][b]
#pragma unroll
        for (int r = 0; r < 4; r++) {
            int flat = tid + r * 256;          // 0..1023 float4s
            int b = flat >> 5, kq = flat & 31;
            float4 v = *(const float4*)(x + ((size_t)b * TT + t) * 1024 + g * 128 + kq * 4);
            Xs[(kq * 4 + 0) * PADX + b] = v.x;
            Xs[(kq * 4 + 1) * PADX + b] = v.y;
            Xs[(kq * 4 + 2) * PADX + b] = v.z;
            Xs[(kq * 4 + 3) * PADX + b] = v.w;
        }
        __syncthreads();

        ull acc[6][4];
#pragma unroll
        for (int p = 0; p < 6; p++) {
            ull binit = pk(bias[2 * p], bias[2 * p + 1]);
#pragma unroll
            for (int b = 0; b < 4; b++) acc[p][b] = binit;
        }

#pragma unroll 4
        for (int k = 0; k < 128; k++) {
            const ulonglong2* wp = (const ulonglong2*)(Ws + k * PADW + ro);
            ulonglong2 wA = wp[0];          // pairs (o,o+1),(o+2,o+3)
            ulonglong2 wB = wp[1];
            ulonglong2 wC = wp[2];
            float2 xa = *(const float2*)(Xs + k * PADX + bb);
            float2 xb = *(const float2*)(Xs + k * PADX + bb + 2);
            ull xd0 = pk(xa.x, xa.x);
            ull xd1 = pk(xa.y, xa.y);
            ull xd2 = pk(xb.x, xb.x);
            ull xd3 = pk(xb.y, xb.y);

            fma2(acc[0][0], wA.x, xd0); fma2(acc[0][1], wA.x, xd1);
            fma2(acc[0][2], wA.x, xd2); fma2(acc[0][3], wA.x, xd3);
            fma2(acc[1][0], wA.y, xd0); fma2(acc[1][1], wA.y, xd1);
            fma2(acc[1][2], wA.y, xd2); fma2(acc[1][3], wA.y, xd3);
            fma2(acc[2][0], wB.x, xd0); fma2(acc[2][1], wB.x, xd1);
            fma2(acc[2][2], wB.x, xd2); fma2(acc[2][3], wB.x, xd3);
            fma2(acc[3][0], wB.y, xd0); fma2(acc[3][1], wB.y, xd1);
            fma2(acc[3][2], wB.y, xd2); fma2(acc[3][3], wB.y, xd3);
            fma2(acc[4][0], wC.x, xd0); fma2(acc[4][1], wC.x, xd1);
            fma2(acc[4][2], wC.x, xd2); fma2(acc[4][3], wC.x, xd3);
            fma2(acc[5][0], wC.y, xd0); fma2(acc[5][1], wC.y, xd1);
            fma2(acc[5][2], wC.y, xd2); fma2(acc[5][3], wC.y, xd3);
        }

        // Store gx[t][g][o][b]
        float* outp = g_gx + ((size_t)t * GR + g) * ROWS * BATCH;
#pragma unroll
        for (int p = 0; p < 6; p++) {
            float2 u0 = up(acc[p][0]);
            float2 u1 = up(acc[p][1]);
            float2 u2 = up(acc[p][2]);
            float2 u3 = up(acc[p][3]);
            float4 v0 = make_float4(u0.x, u1.x, u2.x, u3.x);
            float4 v1 = make_float4(u0.y, u1.y, u2.y, u3.y);
            *(float4*)(outp + (ro + 2 * p)     * BATCH + bb) = v0;
            *(float4*)(outp + (ro + 2 * p + 1) * BATCH + bb) = v1;
        }
        __syncthreads();
    }
}

// ============================================================================
// Phase 2: recurrence. Grid: 128 CTAs = (g 0..7) x (bp 0..15).
// 512 threads: j = tid>>2 (output unit), q = tid&3 (k-chunk of 32, in LANE
// bits so the cross-q reduction is 2 rounds of shfl.bfly — no smem, no extra
// barrier). W_hh register-resident as f32x2 k-pairs. Ping-pong h buffers ->
// ONE __syncthreads per step. All threads do gate math (4x redundant);
// lanes q=0/1 write h, q=2/3 write out.
// h buffers swizzled: chunk c (32 floats) at offset c*36 -> the 4 q-lanes'
// LDS.128 hit disjoint banks.
// ============================================================================
__global__ void __launch_bounds__(512, 1)
gru_kernel(const float* __restrict__ state,
           const float* __restrict__ W_hh,
           const float* __restrict__ b_hh,
           float* __restrict__ out)
{
    __shared__ __align__(16) float Hb0[2][HPAD];
    __shared__ __align__(16) float Hb1[2][HPAD];

    const int g   = blockIdx.x >> 4;
    const int bp  = blockIdx.x & 15;
    const int tid = threadIdx.x;
    const int j   = tid >> 2;       // 0..127
    const int q   = tid & 3;        // 0..3
    const int b0  = bp * 2;
    const int b1  = b0 + 1;

    // ---- load W_hh rows (j, 128+j, 256+j), cols q*32..q*32+31, as k-pairs ----
    ull wr[16], wz[16], wn[16];
    {
        const float* base = W_hh + (size_t)g * ROWS * 128 + q * 32;
        const float* pr = base + (size_t)(j)       * 128;
        const float* pz = base + (size_t)(128 + j) * 128;
        const float* pn = base + (size_t)(256 + j) * 128;
#pragma unroll
        for (int i = 0; i < 8; i++) {
            ulonglong2 a = *(const ulonglong2*)(pr + i * 4);
            wr[2 * i] = a.x; wr[2 * i + 1] = a.y;
            ulonglong2 b = *(const ulonglong2*)(pz + i * 4);
            wz[2 * i] = b.x; wz[2 * i + 1] = b.y;
            ulonglong2 c = *(const ulonglong2*)(pn + i * 4);
            wn[2 * i] = c.x; wn[2 * i + 1] = c.y;
        }
    }

    const float bhr = b_hh[g * ROWS + j];
    const float bhz = b_hh[g * ROWS + 128 + j];
    const float bhn = b_hh[g * ROWS + 256 + j];

    const int jsw = (j >> 5) * 36 + (j & 31);   // swizzled index for unit j

    // init h (buffer 0)
    if (q == 0) Hb0[0][jsw] = state[((size_t)g * 32 + b0) * 128 + j];
    if (q == 1) Hb1[0][jsw] = state[((size_t)g * 32 + b1) * 128 + j];
    __syncthreads();

    const float* gx_g = g_gx + (size_t)g * ROWS * BATCH + b0;
    const int qoff = q * 36;
    int p = 0;

    for (int t = 0; t < TT; t++) {
        // gx for this step (all lanes, 4x redundant) — hidden under K-loop
        const float* gp = gx_g + (size_t)t * (GR * ROWS * BATCH);
        float2 gxr = *(const float2*)(gp + (size_t)(j)       * BATCH);
        float2 gxz = *(const float2*)(gp + (size_t)(128 + j) * BATCH);
        float2 gxn = *(const float2*)(gp + (size_t)(256 + j) * BATCH);
        float h0old = Hb0[p][jsw];
        float h1old = Hb1[p][jsw];

        ull ar0 = 0, az0 = 0, an0 = 0;
        ull ar1 = 0, az1 = 0, an1 = 0;

#pragma unroll
        for (int i = 0; i < 8; i++) {
            ulonglong2 h0 = *(const ulonglong2*)(&Hb0[p][qoff + i * 4]);
            ulonglong2 h1 = *(const ulonglong2*)(&Hb1[p][qoff + i * 4]);
            fma2(ar0, wr[2 * i],     h0.x);
            fma2(az0, wz[2 * i],     h0.x);
            fma2(an0, wn[2 * i],     h0.x);
            fma2(ar1, wr[2 * i],     h1.x);
            fma2(az1, wz[2 * i],     h1.x);
            fma2(an1, wn[2 * i],     h1.x);
            fma2(ar0, wr[2 * i + 1], h0.y);
            fma2(az0, wz[2 * i + 1], h0.y);
            fma2(an0, wn[2 * i + 1], h0.y);
            fma2(ar1, wr[2 * i + 1], h1.y);
            fma2(az1, wz[2 * i + 1], h1.y);
            fma2(an1, wn[2 * i + 1], h1.y);
        }

        // collapse packed halves, then bfly-reduce over the 4 q lanes
        float sr0 = hadd(ar0), sz0 = hadd(az0), sn0 = hadd(an0);
        float sr1 = hadd(ar1), sz1 = hadd(az1), sn1 = hadd(an1);

        sr0 += __shfl_xor_sync(0xffffffffu, sr0, 1);
        sz0 += __shfl_xor_sync(0xffffffffu, sz0, 1);
        sn0 += __shfl_xor_sync(0xffffffffu, sn0, 1);
        sr1 += __shfl_xor_sync(0xffffffffu, sr1, 1);
        sz1 += __shfl_xor_sync(0xffffffffu, sz1, 1);
        sn1 += __shfl_xor_sync(0xffffffffu, sn1, 1);
        sr0 += __shfl_xor_sync(0xffffffffu, sr0, 2);
        sz0 += __shfl_xor_sync(0xffffffffu, sz0, 2);
        sn0 += __shfl_xor_sync(0xffffffffu, sn0, 2);
        sr1 += __shfl_xor_sync(0xffffffffu, sr1, 2);
        sz1 += __shfl_xor_sync(0xffffffffu, sz1, 2);
        sn1 += __shfl_xor_sync(0xffffffffu, sn1, 2);

        // gate math (all lanes, redundant)
        float r0 = sigm(gxr.x + sr0 + bhr);
        float z0 = sigm(gxz.x + sz0 + bhz);
        float n0 = tanh_(gxn.x + r0 * (sn0 + bhn));
        float h0n = n0 + z0 * (h0old - n0);

        float r1 = sigm(gxr.y + sr1 + bhr);
        float z1 = sigm(gxz.y + sz1 + bhz);
        float n1 = tanh_(gxn.y + r1 * (sn1 + bhn));
        float h1n = n1 + z1 * (h1old - n1);

        const int np = p ^ 1;
        if (q == 0) {
            Hb0[np][jsw] = h0n;
        } else if (q == 1) {
            Hb1[np][jsw] = h1n;
        } else if (q == 2) {
            out[((size_t)b0 * TT + t) * 1024 + g * 128 + j] = h0n;
        } else {
            out[((size_t)b1 * TT + t) * 1024 + g * 128 + j] = h1n;
        }
        __syncthreads();
        p = np;
    }

    // h_out[g][b][j] appended after y
    float* hop = out + (size_t)BATCH * TT * 1024;
    if (q == 0) hop[((size_t)g * 32 + b0) * 128 + j] = Hb0[p][jsw];
    if (q == 1) hop[((size_t)g * 32 + b1) * 128 + j] = Hb1[p][jsw];
}

extern "C" void kernel_launch(void* const* d_in, const int* in_sizes, int n_in,
                              void* d_out, int out_size)
{
    const float* x     = (const float*)d_in[0];
    const float* state = (const float*)d_in[1];
    const float* W_ih  = (const float*)d_in[2];
    const float* W_hh  = (const float*)d_in[3];
    const float* b_ih  = (const float*)d_in[4];
    const float* b_hh  = (const float*)d_in[5];
    float* out = (float*)d_out;

    const int smem1 = (128 * PADW + 128 * PADX) * 4;   // 216,064 B

    cudaFuncSetAttribute(gx_kernel, cudaFuncAttributeMaxDynamicSharedMemorySize, smem1);

    gx_kernel<<<128, 256, smem1>>>(x, W_ih, b_ih);
    gru_kernel<<<128, 512>>>(state, W_hh, b_hh, out);
}

// round 4
// speedup vs baseline: 1.0701x; 1.0701x over previous
#include <cuda_runtime.h>
#include <cuda_bf16.h>
#include <cstdint>

#define GR 8
#define BATCH 32
#define TT 512
#define ROWS 384          // 3 * 128
#define PADW 386          // phase-1 weight smem row stride (floats)
#define XROW 132          // phase-1 x smem row stride (floats)
#define HPAD 144          // phase-2 h buffer stride (4 chunks of 32, stride 36)

typedef unsigned long long ull;

// 201 MB scratch for gx[t][g][o][b]
__device__ float g_gx[(size_t)TT * GR * ROWS * BATCH];

__device__ __forceinline__ ull pk(float lo, float hi) {
    ull r;
    asm("mov.b64 %0, {%1, %2};" : "=l"(r) : "f"(lo), "f"(hi));
    return r;
}
__device__ __forceinline__ float2 up(ull v) {
    float2 r;
    asm("mov.b64 {%0, %1}, %2;" : "=f"(r.x), "=f"(r.y) : "l"(v));
    return r;
}
__device__ __forceinline__ void fma2(ull& d, ull a, ull b) {
    asm("fma.rn.f32x2 %0, %1, %2, %0;" : "+l"(d) : "l"(a), "l"(b));
}
__device__ __forceinline__ float sigm(float x) {
    return __fdividef(1.0f, 1.0f + __expf(-x));
}
__device__ __forceinline__ float tanh_(float x) {
    return 1.0f - __fdividef(2.0f, __expf(2.0f * x) + 1.0f);
}
__device__ __forceinline__ float hadd(ull v) {
    float2 u = up(v);
    return u.x + u.y;
}
__device__ __forceinline__ unsigned sptr(const void* p) {
    return (unsigned)__cvta_generic_to_shared(p);
}
__device__ __forceinline__ void cpa8(unsigned d, const void* s) {
    asm volatile("cp.async.ca.shared.global [%0], [%1], 8;" :: "r"(d), "l"(s));
}
__device__ __forceinline__ void cpa16(unsigned d, const void* s) {
    asm volatile("cp.async.cg.shared.global [%0], [%1], 16;" :: "r"(d), "l"(s));
}
__device__ __forceinline__ void cpcommit() { asm volatile("cp.async.commit_group;" ::: "memory"); }
__device__ __forceinline__ void cpwait0()  { asm volatile("cp.async.wait_group 0;" ::: "memory"); }
__device__ __forceinline__ void cpwait1()  { asm volatile("cp.async.wait_group 1;" ::: "memory"); }

// ============================================================================
// Phase 1: gx[t][g][o][b] = b_ih[g][o] + sum_i W_ih[g][o][i] * x[b][t][g*128+i]
// 128 CTAs = (tb 0..15) x (g 0..7), 512 threads (4 warps/SMSP).
// x staged [b][XROW] untransposed via cp.async.16, double-buffered; W_ih[g]
// transposed in smem. Thread = (w, rsub, bq): 6 rows (ro..ro+5) x 4 batches
// {bq, bq+8, bq+16, bq+24} (strided -> conflict-free x LDS).
// ============================================================================
__global__ void __launch_bounds__(512, 1)
gx_kernel(const float* __restrict__ x,
          const float* __restrict__ W_ih,
          const float* __restrict__ b_ih)
{
    extern __shared__ float sm[];
    float* Ws = sm;                       // [128][PADW]  W[k][o]
    float* Xs = sm + 128 * PADW;          // [2][32][XROW] x[b][k]

    const int g  = blockIdx.x & 7;
    const int tb = blockIdx.x >> 3;
    const int tid = threadIdx.x;

    const float* Wg = W_ih + (size_t)g * ROWS * 128;
    for (int idx = tid; idx < ROWS * 128; idx += 512) {
        int o = idx >> 7, k = idx & 127;
        Ws[k * PADW + o] = Wg[idx];
    }

    const int w    = tid >> 5;
    const int lane = tid & 31;
    const int rsub = lane >> 3;           // 0..3
    const int bq   = lane & 7;            // 0..7
    const int ro   = w * 24 + rsub * 6;   // 6 rows per thread

    float bias[6];
#pragma unroll
    for (int i = 0; i < 6; i++) bias[i] = b_ih[g * ROWS + ro + i];

    // prologue: stage x for t = tb*32 into buffer 0
    {
        const int t0 = tb * 32;
#pragma unroll
        for (int r = 0; r < 2; r++) {
            int c = tid + r * 512;        // 0..1023 16B chunks
            int b = c >> 5, kq = c & 31;
            cpa16(sptr(Xs + b * XROW + kq * 4),
                  x + ((size_t)b * TT + t0) * 1024 + g * 128 + kq * 4);
        }
    }
    cpcommit();

    for (int tt = 0; tt < 32; tt++) {
        const int t = tb * 32 + tt;
        const float* Xc = Xs + (tt & 1) * (32 * XROW);

        cpwait0();          // buffer (tt&1) complete (committed last iter)
        __syncthreads();    // visible to all; also covers Ws on iter 0

        if (tt < 31) {
            float* Xn = Xs + ((tt + 1) & 1) * (32 * XROW);
#pragma unroll
            for (int r = 0; r < 2; r++) {
                int c = tid + r * 512;
                int b = c >> 5, kq = c & 31;
                cpa16(sptr(Xn + b * XROW + kq * 4),
                      x + ((size_t)b * TT + t + 1) * 1024 + g * 128 + kq * 4);
            }
        }
        cpcommit();

        ull acc[3][4];
#pragma unroll
        for (int p = 0; p < 3; p++) {
            ull binit = pk(bias[2 * p], bias[2 * p + 1]);
#pragma unroll
            for (int i = 0; i < 4; i++) acc[p][i] = binit;
        }

#pragma unroll 4
        for (int k = 0; k < 128; k++) {
            const float* wb = Ws + k * PADW + ro;
            ull w0 = *(const ull*)(wb);
            ull w1 = *(const ull*)(wb + 2);
            ull w2 = *(const ull*)(wb + 4);
            float x0 = Xc[(bq     ) * XROW + k];
            float x1 = Xc[(bq +  8) * XROW + k];
            float x2 = Xc[(bq + 16) * XROW + k];
            float x3 = Xc[(bq + 24) * XROW + k];
            ull d0 = pk(x0, x0), d1 = pk(x1, x1), d2 = pk(x2, x2), d3 = pk(x3, x3);
            fma2(acc[0][0], w0, d0); fma2(acc[0][1], w0, d1);
            fma2(acc[0][2], w0, d2); fma2(acc[0][3], w0, d3);
            fma2(acc[1][0], w1, d0); fma2(acc[1][1], w1, d1);
            fma2(acc[1][2], w1, d2); fma2(acc[1][3], w1, d3);
            fma2(acc[2][0], w2, d0); fma2(acc[2][1], w2, d1);
            fma2(acc[2][2], w2, d2); fma2(acc[2][3], w2, d3);
        }

        float* outp = g_gx + ((size_t)t * GR + g) * ROWS * BATCH;
#pragma unroll
        for (int p = 0; p < 3; p++) {
#pragma unroll
            for (int i = 0; i < 4; i++) {
                float2 u = up(acc[p][i]);
                outp[(ro + 2 * p)     * BATCH + bq + 8 * i] = u.x;
                outp[(ro + 2 * p + 1) * BATCH + bq + 8 * i] = u.y;
            }
        }
    }
}

// ============================================================================
// Phase 2: recurrence. 128 CTAs = (g) x (bp: batches 2bp, 2bp+1), 512 threads:
// j = tid>>2, q = tid&3 (k-chunk of 32 in lane bits). W_hh register-resident
// (f32x2 k-pairs). gx staged via cp.async into a triple-buffered smem ring,
// prefetched 2 steps ahead. Reduce-scatter over q lanes (6 shfl): lanes q<2
// end with batch-b0 sums, q>=2 with b1 -> gate math once per batch-pair.
// q0 writes h_b0, q1 out_b0, q2 h_b1, q3 out_b1. One barrier per step.
// ============================================================================
__global__ void __launch_bounds__(512, 1)
gru_kernel(const float* __restrict__ state,
           const float* __restrict__ W_hh,
           const float* __restrict__ b_hh,
           float* __restrict__ out)
{
    __shared__ __align__(16) float Hb0[2][HPAD];
    __shared__ __align__(16) float Hb1[2][HPAD];
    __shared__ __align__(16) float Gs[3][ROWS * 2];   // [buf][o*2 + b]  9 KB

    const int g   = blockIdx.x >> 4;
    const int bp  = blockIdx.x & 15;
    const int tid = threadIdx.x;
    const int j   = tid >> 2;
    const int q   = tid & 3;
    const int b0  = bp * 2;

    // weights: rows (j, 128+j, 256+j), cols q*32..q*32+31, as k-pairs
    ull wr[16], wz[16], wn[16];
    {
        const float* base = W_hh + (size_t)g * ROWS * 128 + q * 32;
        const float* pr = base + (size_t)(j)       * 128;
        const float* pz = base + (size_t)(128 + j) * 128;
        const float* pn = base + (size_t)(256 + j) * 128;
#pragma unroll
        for (int i = 0; i < 8; i++) {
            ulonglong2 a = *(const ulonglong2*)(pr + i * 4);
            wr[2 * i] = a.x; wr[2 * i + 1] = a.y;
            ulonglong2 b = *(const ulonglong2*)(pz + i * 4);
            wz[2 * i] = b.x; wz[2 * i + 1] = b.y;
            ulonglong2 c = *(const ulonglong2*)(pn + i * 4);
            wn[2 * i] = c.x; wn[2 * i + 1] = c.y;
        }
    }

    const float bhr = b_hh[g * ROWS + j];
    const float bhz = b_hh[g * ROWS + 128 + j];
    const float bhn = b_hh[g * ROWS + 256 + j];

    const int jsw = (j >> 5) * 36 + (j & 31);

    if (q == 0) Hb0[0][jsw] = state[((size_t)g * 32 + b0) * 128 + j];
    if (q == 1) Hb1[0][jsw] = state[((size_t)g * 32 + b0 + 1) * 128 + j];

    const size_t stride_t = (size_t)GR * ROWS * BATCH;
    const float* gx0 = g_gx + (size_t)g * ROWS * BATCH + b0;   // + t*stride_t + o*BATCH

    // prologue: stage gx for t=0 (buf0) and t=1 (buf1)
    if (tid < ROWS) cpa8(sptr(&Gs[0][tid * 2]), gx0 + tid * BATCH);
    cpcommit();
    if (tid < ROWS) cpa8(sptr(&Gs[1][tid * 2]), gx0 + stride_t + tid * BATCH);
    cpcommit();
    cpwait1();          // group(t=0) complete
    __syncthreads();    // h init + Gs[0] visible

    const int qoff = q * 36;
    int p = 0, cb = 0;

    for (int t = 0; t < TT; t++) {
        // stage gx for t+2 into buffer (cb+2)%3
        {
            int nb = cb + 2; if (nb >= 3) nb -= 3;
            if (t + 2 < TT && tid < ROWS)
                cpa8(sptr(&Gs[nb][tid * 2]), gx0 + (size_t)(t + 2) * stride_t + tid * BATCH);
            cpcommit();
        }

        ull ar0 = 0, az0 = 0, an0 = 0;
        ull ar1 = 0, az1 = 0, an1 = 0;

#pragma unroll
        for (int i = 0; i < 8; i++) {
            ulonglong2 h0 = *(const ulonglong2*)(&Hb0[p][qoff + i * 4]);
            ulonglong2 h1 = *(const ulonglong2*)(&Hb1[p][qoff + i * 4]);
            fma2(ar0, wr[2 * i],     h0.x);
            fma2(az0, wz[2 * i],     h0.x);
            fma2(an0, wn[2 * i],     h0.x);
            fma2(ar1, wr[2 * i],     h1.x);
            fma2(az1, wz[2 * i],     h1.x);
            fma2(an1, wn[2 * i],     h1.x);
            fma2(ar0, wr[2 * i + 1], h0.y);
            fma2(az0, wz[2 * i + 1], h0.y);
            fma2(an0, wn[2 * i + 1], h0.y);
            fma2(ar1, wr[2 * i + 1], h1.y);
            fma2(az1, wz[2 * i + 1], h1.y);
            fma2(an1, wn[2 * i + 1], h1.y);
        }

        // collapse packed halves
        float sr0 = hadd(ar0), sz0 = hadd(az0), sn0 = hadd(an0);
        float sr1 = hadd(ar1), sz1 = hadd(az1), sn1 = hadd(an1);

        // reduce-scatter over 4 q lanes: q<2 -> full b0 sums, q>=2 -> full b1
        const bool hi = (q & 2) != 0;
        float vr = hi ? sr0 : sr1;
        float vz = hi ? sz0 : sz1;
        float vn = hi ? sn0 : sn1;
        float kr = hi ? sr1 : sr0;
        float kz = hi ? sz1 : sz0;
        float kn = hi ? sn1 : sn0;
        kr += __shfl_xor_sync(0xffffffffu, vr, 2);
        kz += __shfl_xor_sync(0xffffffffu, vz, 2);
        kn += __shfl_xor_sync(0xffffffffu, vn, 2);
        kr += __shfl_xor_sync(0xffffffffu, kr, 1);
        kz += __shfl_xor_sync(0xffffffffu, kz, 1);
        kn += __shfl_xor_sync(0xffffffffu, kn, 1);

        // my batch's gx + h_old
        const int myb = q >> 1;
        float gr_ = Gs[cb][(j)       * 2 + myb];
        float gz_ = Gs[cb][(128 + j) * 2 + myb];
        float gn_ = Gs[cb][(256 + j) * 2 + myb];
        const float* hb = hi ? Hb1[p] : Hb0[p];
        float hold = hb[jsw];

        float r = sigm(gr_ + kr + bhr);
        float z = sigm(gz_ + kz + bhz);
        float n = tanh_(gn_ + r * (kn + bhn));
        float hn = n + z * (hold - n);

        const int np = p ^ 1;
        if (q == 0) {
            Hb0[np][jsw] = hn;
        } else if (q == 1) {
            out[((size_t)b0 * TT + t) * 1024 + g * 128 + j] = hn;
        } else if (q == 2) {
            Hb1[np][jsw] = hn;
        } else {
            out[((size_t)(b0 + 1) * TT + t) * 1024 + g * 128 + j] = hn;
        }

        cpwait1();          // group for t+1 complete (issued last step)
        __syncthreads();    // h[np] + Gs[t+1] visible
        p = np;
        cb = cb + 1; if (cb >= 3) cb -= 3;
    }

    // h_out[g][b][j] appended after y
    float* hop = out + (size_t)BATCH * TT * 1024;
    if (q == 0) hop[((size_t)g * 32 + b0) * 128 + j]     = Hb0[p][jsw];
    if (q == 1) hop[((size_t)g * 32 + b0 + 1) * 128 + j] = Hb1[p][jsw];
}

extern "C" void kernel_launch(void* const* d_in, const int* in_sizes, int n_in,
                              void* d_out, int out_size)
{
    const float* x     = (const float*)d_in[0];
    const float* state = (const float*)d_in[1];
    const float* W_ih  = (const float*)d_in[2];
    const float* W_hh  = (const float*)d_in[3];
    const float* b_ih  = (const float*)d_in[4];
    const float* b_hh  = (const float*)d_in[5];
    float* out = (float*)d_out;

    const int smem1 = (128 * PADW + 2 * 32 * XROW) * 4;   // 231,424 B

    cudaFuncSetAttribute(gx_kernel, cudaFuncAttributeMaxDynamicSharedMemorySize, smem1);

    gx_kernel<<<128, 512, smem1>>>(x, W_ih, b_ih);
    gru_kernel<<<128, 512>>>(state, W_hh, b_hh, out);
}